// round 2
// baseline (speedup 1.0000x reference)
#include <cuda_runtime.h>
#include <cuda_bf16.h>

// Leapfrog (kick-drift-kick) integrator, GM = 1, A_SCALE = 1.
// One thread per PARTICLE, integrating BOTH its trail (s=0) and lead (s=1)
// trajectories: two independent dependency chains for ILP, shared dt, and
// the two output rows (2i, 2i+1) are contiguous -> 3x float4 stores.
//
// Interior kicks are fused: p_new = p_half + h*a ; next p_half = p_new + h*a
// (same a) => one p += dt*a per interior step. Kick coefficient is folded
// into the force scalar: a = -f*q, p += c*a  ==  p = fma(c*(-f), q, p).

__device__ __forceinline__ float rsqrt_approx(float x) {
    float y;
    asm("rsqrt.approx.f32 %0, %1;" : "=f"(y) : "f"(x));
    return y;
}

__device__ __forceinline__ float rcp_approx(float x) {
    float y;
    asm("rcp.approx.f32 %0, %1;" : "=f"(y) : "f"(x));
    return y;
}

struct Traj {
    float qx, qy, qz, px, py, pz;
};

// Returns cf = c / (r(r+1)^2 + 1e-12), with r = |q|, using
// r + 2r^2 + r^3 = s*(u + 2 + r)  (s = |q|^2, u = 1/sqrt(s), r = s*u).
// Caller passes c = -dt (or -dt/2) so the kick is p = fma(cf, q, p).
__device__ __forceinline__ float kick_coeff(const Traj& t, float c) {
    float s = fmaf(t.qx, t.qx, fmaf(t.qy, t.qy, fmaf(t.qz, t.qz, 1e-30f)));
    float u = rsqrt_approx(s);           // MUFU
    float r = s * u;                     // sqrt(s)
    float w = (u + 2.0f) + r;
    float den = fmaf(s, w, 1e-12f);
    return c * rcp_approx(den);          // MUFU
}

__device__ __forceinline__ void kick(Traj& t, float cf) {
    t.px = fmaf(cf, t.qx, t.px);
    t.py = fmaf(cf, t.qy, t.py);
    t.pz = fmaf(cf, t.qz, t.pz);
}

__device__ __forceinline__ void drift(Traj& t, float dt) {
    t.qx = fmaf(dt, t.px, t.qx);
    t.qy = fmaf(dt, t.py, t.qy);
    t.qz = fmaf(dt, t.pz, t.qz);
}

// n_full interior steps with full-dt kicks, then one final half kick.
__device__ __forceinline__ void integrate_pair(Traj& a, Traj& b,
                                               float dt, float ndt, float nhdt,
                                               int n_full) {
    // Prime: half kick with accel at q0.
    kick(a, kick_coeff(a, nhdt));
    kick(b, kick_coeff(b, nhdt));

    #pragma unroll 3
    for (int k = 0; k < n_full; ++k) {
        drift(a, dt);
        drift(b, dt);
        float ca = kick_coeff(a, ndt);
        float cb = kick_coeff(b, ndt);
        kick(a, ca);
        kick(b, cb);
    }

    // Last step: drift + half kick.
    drift(a, dt);
    drift(b, dt);
    float ca = kick_coeff(a, nhdt);
    float cb = kick_coeff(b, nhdt);
    kick(a, ca);
    kick(b, cb);
}

__device__ __forceinline__ Traj load_row(const float* __restrict__ w, int i) {
    const float2* src = reinterpret_cast<const float2*>(w + (size_t)i * 6);
    float2 v0 = src[0], v1 = src[1], v2 = src[2];
    Traj t;
    t.qx = v0.x; t.qy = v0.y; t.qz = v1.x;
    t.px = v1.y; t.py = v2.x; t.pz = v2.y;
    return t;
}

__global__ void __launch_bounds__(128)
stream_integrate_kernel(const float* __restrict__ ts,
                        const float* __restrict__ w_lead,
                        const float* __restrict__ w_trail,
                        const int*   __restrict__ n_steps_p,
                        float* __restrict__ out,
                        int n) {
    int i = blockIdx.x * blockDim.x + threadIdx.x;
    if (i >= n) return;

    Traj tr = load_row(w_trail, i);   // output row 2i
    Traj ld = load_row(w_lead,  i);   // output row 2i+1

    float t_f = __ldg(ts + (n - 1)) + 0.001f;   // broadcast, L2-cached
    int   nst = *n_steps_p;
    float dt  = (t_f - ts[i]) / (float)nst;     // shared by both trajectories
    float ndt = -dt;
    float nhdt = 0.5f * ndt;

    if (nst == 64) {
        integrate_pair(tr, ld, dt, ndt, nhdt, 63);
    } else if (nst > 0) {
        integrate_pair(tr, ld, dt, ndt, nhdt, nst - 1);
    }

    // Rows 2i and 2i+1 are 12 contiguous floats at out + 12*i (16B aligned).
    float4* dst = reinterpret_cast<float4*>(out + (size_t)i * 12);
    dst[0] = make_float4(tr.qx, tr.qy, tr.qz, tr.px);
    dst[1] = make_float4(tr.py, tr.pz, ld.qx, ld.qy);
    dst[2] = make_float4(ld.qz, ld.px, ld.py, ld.pz);
}

extern "C" void kernel_launch(void* const* d_in, const int* in_sizes, int n_in,
                              void* d_out, int out_size) {
    const float* ts      = (const float*)d_in[0];
    const float* w_lead  = (const float*)d_in[1];
    const float* w_trail = (const float*)d_in[2];
    const int*   n_steps = (const int*)d_in[3];
    float*       out     = (float*)d_out;

    int n = in_sizes[0];                 // 65536 particles
    int block = 128;
    int grid = (n + block - 1) / block;  // 512 CTAs
    stream_integrate_kernel<<<grid, block>>>(ts, w_lead, w_trail, n_steps, out, n);
}

// round 3
// speedup vs baseline: 1.4310x; 1.4310x over previous
#include <cuda_runtime.h>
#include <cuda_bf16.h>

// Leapfrog (kick-drift-kick) integrator, GM = 1, A_SCALE = 1.
// One thread per (particle, stream) pair: tid = 2*i + s, s=0 -> trail,
// s=1 -> lead. That is exactly the output row index after the reference's
// stack([trail, lead], axis=1).reshape(2N, 6), so stores are contiguous.
//
// Interior kicks are fused: p_new = p_half + h*a ; next p_half' = p_new + h*a
// with the SAME a  =>  one p += dt*a per interior step (half kicks only at
// the two ends). The kick coefficient is folded into the force scalar:
// a = -f*q, p += c*a  ==  p = fma(-c*f, q, p).

__device__ __forceinline__ float rsqrt_approx(float x) {
    float y;
    asm("rsqrt.approx.f32 %0, %1;" : "=f"(y) : "f"(x));
    return y;
}

__device__ __forceinline__ float rcp_approx(float x) {
    float y;
    asm("rcp.approx.f32 %0, %1;" : "=f"(y) : "f"(x));
    return y;
}

struct State {
    float qx, qy, qz, px, py, pz;
};

// cf = c / (r(r+1)^2 + 1e-12), r = |q|.  Uses
// r + 2r^2 + r^3 = s*(u + 2 + r)  with s = |q|^2, u = rsqrt(s), r = s*u.
// Caller passes c = -dt (or -dt/2), so the kick is p = fma(cf, q, p).
// The 1e-30 seed keeps s > 0 so u stays finite; at q ~ 0 we get r ~ 0,
// den ~ 1e-12, matching the reference guard.
__device__ __forceinline__ float kick_coeff(const State& t, float c) {
    float s = fmaf(t.qx, t.qx, fmaf(t.qy, t.qy, fmaf(t.qz, t.qz, 1e-30f)));
    float u = rsqrt_approx(s);           // MUFU
    float r = s * u;                     // sqrt(s)
    float w = (u + 2.0f) + r;
    float den = fmaf(s, w, 1e-12f);
    return c * rcp_approx(den);          // MUFU
}

__device__ __forceinline__ void kick(State& t, float cf) {
    t.px = fmaf(cf, t.qx, t.px);
    t.py = fmaf(cf, t.qy, t.py);
    t.pz = fmaf(cf, t.qz, t.pz);
}

__device__ __forceinline__ void drift(State& t, float dt) {
    t.qx = fmaf(dt, t.px, t.qx);
    t.qy = fmaf(dt, t.py, t.qy);
    t.qz = fmaf(dt, t.pz, t.qz);
}

// Interior step: drift then full-dt kick.
__device__ __forceinline__ void step_full(State& t, float dt, float ndt) {
    drift(t, dt);
    kick(t, kick_coeff(t, ndt));
}

__global__ void __launch_bounds__(256)
stream_integrate_kernel(const float* __restrict__ ts,
                        const float* __restrict__ w_lead,
                        const float* __restrict__ w_trail,
                        const int*   __restrict__ n_steps_p,
                        float* __restrict__ out,
                        int n) {
    int tid = blockIdx.x * blockDim.x + threadIdx.x;
    if (tid >= 2 * n) return;

    int i = tid >> 1;       // particle index
    int s = tid & 1;        // 0 = trail, 1 = lead
    const float* w0 = s ? w_lead : w_trail;

    // Row i*6 floats = 24*i bytes -> 8-byte aligned: 3x float2 loads.
    const float2* src = reinterpret_cast<const float2*>(w0 + (size_t)i * 6);
    float2 v0 = src[0];
    float2 v1 = src[1];
    float2 v2 = src[2];

    State st;
    st.qx = v0.x; st.qy = v0.y; st.qz = v1.x;
    st.px = v1.y; st.py = v2.x; st.pz = v2.y;

    float t_f = __ldg(ts + (n - 1)) + 0.001f;   // broadcast, L2-cached
    int   nst = *n_steps_p;
    float dt  = (t_f - ts[i]) / (float)nst;
    float ndt  = -dt;
    float nhdt = 0.5f * ndt;

    // Opening half kick with accel(q0).
    kick(st, kick_coeff(st, nhdt));

    if (nst == 64) {
        #pragma unroll 8
        for (int k = 0; k < 63; ++k) step_full(st, dt, ndt);
    } else {
        for (int k = 0; k < nst - 1; ++k) step_full(st, dt, ndt);
    }

    // Closing step: drift + half kick.
    drift(st, dt);
    kick(st, kick_coeff(st, nhdt));

    float2* dst = reinterpret_cast<float2*>(out + (size_t)tid * 6);
    dst[0] = make_float2(st.qx, st.qy);
    dst[1] = make_float2(st.qz, st.px);
    dst[2] = make_float2(st.py, st.pz);
}

extern "C" void kernel_launch(void* const* d_in, const int* in_sizes, int n_in,
                              void* d_out, int out_size) {
    const float* ts      = (const float*)d_in[0];
    const float* w_lead  = (const float*)d_in[1];
    const float* w_trail = (const float*)d_in[2];
    const int*   n_steps = (const int*)d_in[3];
    float*       out     = (float*)d_out;

    int n = in_sizes[0];                 // 65536 particles
    int total = 2 * n;                   // one thread per (particle, stream)
    int block = 256;
    int grid = (total + block - 1) / block;   // 1024 CTAs
    stream_integrate_kernel<<<grid, block>>>(ts, w_lead, w_trail, n_steps, out, n);
}